// round 12
// baseline (speedup 1.0000x reference)
#include <cuda_runtime.h>
#include <cuda_bf16.h>
#include <cstdint>
#include <math_constants.h>

#define T_STEPS 1024
#define DIM     300
#define HD1     1024
#define HD2     512
#define VGLOB   50000
#define VSENS   25000
#define NR      128          // rnn CTAs: 1024 = 128*8, 512 = 128*4
#define NREP    8

#define TILES_G 391
#define TILES_S 196
#define PSTR_G  392
#define PSTR_S  200

// ------------------------- device scratch -------------------------
__device__ __align__(16) float g_U1[T_STEPS * HD1];
__device__ __align__(16) float g_h1rep[NREP][4][HD1];   // [replica][slot r&3][row]
__device__ __align__(16) float g_h2rep[NREP][4][HD2];
__device__ __align__(128) unsigned g_cnt1[NREP * 32];   // 8 counter lines, 128B apart
__device__ __align__(128) unsigned g_cnt2[NREP * 32];
__device__ float g_pmaxG[T_STEPS * PSTR_G];
__device__ float g_psumG[T_STEPS * PSTR_G];
__device__ float g_pmaxS[T_STEPS * PSTR_S];
__device__ float g_psumS[T_STEPS * PSTR_S];
__device__ float g_lseG[T_STEPS];
__device__ float g_lseS[T_STEPS];
// bf16 operands for the logits GEMM
__device__ __align__(16) uint16_t g_h2sb[T_STEPS * HD2];
__device__ __align__(16) uint16_t g_Wgb[(size_t)VGLOB * HD2];
__device__ __align__(16) uint16_t g_Wsb[(size_t)VSENS * HD2];

// ------------------------- helpers -------------------------
__device__ __forceinline__ void red_release(unsigned* p, unsigned v) {
    asm volatile("red.release.gpu.global.add.u32 [%0], %1;" :: "l"(p), "r"(v) : "memory");
}
__device__ __forceinline__ unsigned ld_acquire(const unsigned* p) {
    unsigned v;
    asm volatile("ld.acquire.gpu.global.u32 %0, [%1];" : "=r"(v) : "l"(p) : "memory");
    return v;
}
__device__ __forceinline__ void stcg4(float* p, float4 v) {
    asm volatile("st.global.cg.v4.f32 [%0], {%1,%2,%3,%4};"
                 :: "l"(p), "f"(v.x), "f"(v.y), "f"(v.z), "f"(v.w) : "memory");
}

__device__ __forceinline__ void mma_bf16(float c[4], const uint32_t a[4], const uint32_t b[2]) {
    asm volatile(
        "mma.sync.aligned.m16n8k16.row.col.f32.bf16.bf16.f32 "
        "{%0,%1,%2,%3}, {%4,%5,%6,%7}, {%8,%9}, {%0,%1,%2,%3};"
        : "+f"(c[0]), "+f"(c[1]), "+f"(c[2]), "+f"(c[3])
        : "r"(a[0]), "r"(a[1]), "r"(a[2]), "r"(a[3]), "r"(b[0]), "r"(b[1]));
}

__device__ __forceinline__ void cp_async16(void* dst_smem, const void* src, int src_bytes) {
    uint32_t d = (uint32_t)__cvta_generic_to_shared(dst_smem);
    asm volatile("cp.async.cg.shared.global [%0], [%1], 16, %2;"
                 :: "r"(d), "l"(src), "r"(src_bytes));
}
__device__ __forceinline__ void cp_commit() { asm volatile("cp.async.commit_group;"); }
template <int N>
__device__ __forceinline__ void cp_wait() { asm volatile("cp.async.wait_group %0;" :: "n"(N)); }

__device__ __forceinline__ void lse_merge(float& M, float& S, float m, float s) {
    float nm = fmaxf(M, m);
    if (nm == -CUDART_INF_F) { M = nm; S = 0.f; return; }
    S = S * __expf(M - nm) + s * __expf(m - nm);
    M = nm;
}

__device__ __forceinline__ uint32_t pack_bf16(float a, float b) {
    __nv_bfloat16 ba = __float2bfloat16(a), bb = __float2bfloat16(b);
    return (uint32_t)reinterpret_cast<unsigned short&>(ba) |
           ((uint32_t)reinterpret_cast<unsigned short&>(bb) << 16);
}

// ------------------------- init -------------------------
__global__ void init_kernel() {
    int tid = threadIdx.x + blockIdx.x * blockDim.x;
    int stride = gridDim.x * blockDim.x;
    if (tid < NREP * 32) { g_cnt1[tid] = 0u; g_cnt2[tid] = 0u; }
    for (int i = tid; i < NREP * 4 * HD1; i += stride) ((float*)g_h1rep)[i] = 0.f;
    for (int i = tid; i < NREP * 4 * HD2; i += stride) ((float*)g_h2rep)[i] = 0.f;
}

// ------------------------- fp32 -> bf16 weight conversion -------------------------
__global__ void convert_kernel(const float* __restrict__ src, uint16_t* __restrict__ dst, int n4) {
    int i = blockIdx.x * blockDim.x + threadIdx.x;
    int stride = gridDim.x * blockDim.x;
    uint32_t* d32 = (uint32_t*)dst;
    const float4* s4 = (const float4*)src;
    for (; i < n4; i += stride) {
        float4 v = s4[i];
        d32[2 * i]     = pack_bf16(v.x, v.y);
        d32[2 * i + 1] = pack_bf16(v.z, v.w);
    }
}

// ------------------------- U1 = E @ W1e^T + b1 -------------------------
__global__ void __launch_bounds__(256) u1_kernel(const float* __restrict__ X,
                                                 const float* __restrict__ W1,
                                                 const float* __restrict__ b1,
                                                 const int* __restrict__ idx) {
    __shared__ float sA[20][64];
    __shared__ float sB[20][64];
    __shared__ int sidx[64];
    int tid = threadIdx.x;
    int t0 = blockIdx.y * 64, i0 = blockIdx.x * 64;
    if (tid < 64) sidx[tid] = idx[t0 + tid];
    __syncthreads();
    float acc[4][4];
#pragma unroll
    for (int a = 0; a < 4; ++a)
#pragma unroll
        for (int b = 0; b < 4; ++b) acc[a][b] = 0.f;
    int tx = tid & 15, ty = tid >> 4;
    for (int kc = 0; kc < 15; ++kc) {
        int k0 = kc * 20;
        for (int i = tid; i < 1280; i += 256) {
            int k = i >> 6, m = i & 63;
            sA[k][m] = X[(long)sidx[m] * DIM + k0 + k];
            sB[k][m] = W1[(long)(i0 + m) * (DIM + HD1) + k0 + k];
        }
        __syncthreads();
#pragma unroll
        for (int k = 0; k < 20; ++k) {
            float a[4], b[4];
#pragma unroll
            for (int e = 0; e < 4; ++e) { a[e] = sA[k][ty * 4 + e]; b[e] = sB[k][tx * 4 + e]; }
#pragma unroll
            for (int ii = 0; ii < 4; ++ii)
#pragma unroll
                for (int jj = 0; jj < 4; ++jj) acc[ii][jj] += a[ii] * b[jj];
        }
        __syncthreads();
    }
#pragma unroll
    for (int ii = 0; ii < 4; ++ii)
#pragma unroll
        for (int jj = 0; jj < 4; ++jj) {
            int t = t0 + ty * 4 + ii, n = i0 + tx * 4 + jj;
            g_U1[t * HD1 + n] = acc[ii][jj] + b1[n];
        }
}

// ------------------------- persistent RNN core (round-8 structure + per-warp poll) ----
// CTA c owns h1 rows 8c..8c+7 and h2 rows 4c..4c+3. Warps 0-3: h1 chain — each
// warp polls counter line (c+2w)&7 and reads its h1 segment from replica
// (c+2w)&7 (release/acquire pairing exact), __syncwarp only before compute.
// Warps 4-7: h2 chain (single poller + named bar; fully shadowed). Writer
// warp-0/4 lane k stores replica k then red.release line k. 8 replicas;
// slots 4-deep; WAR gated by lagged cnt2 in the writer just before stores.
__global__ void __launch_bounds__(256) rnn_kernel(const float* __restrict__ W1,
                                                  const float* __restrict__ W2,
                                                  const float* __restrict__ b2) {
    __shared__ __align__(16) float sP1[32];   // [q 0..7][warp 0..3]
    __shared__ __align__(16) float sP2[16];   // [q 0..3][warp 0..3]
    int tid = threadIdx.x, c = blockIdx.x;
    int lane = tid & 31;
    int cpy = c & (NREP - 1);

    if (tid < 128) {
        // =================== h1 group (warps 0-3) ===================
        int w = tid >> 5;
        int repw = (c + 2 * w) & (NREP - 1);
        float w1r[8][8];   // [jj][q]
#pragma unroll
        for (int q = 0; q < 8; ++q) {
            const float* p = W1 + (long)(c * 8 + q) * (DIM + HD1) + DIM;
#pragma unroll
            for (int jj = 0; jj < 8; ++jj)
                w1r[jj][q] = p[w * 256 + jj * 32 + lane];
        }

        for (int r = 0; r < T_STEPS; ++r) {
            float u1v = 0.f;
            if (tid < 8) u1v = __ldg(&g_U1[r * HD1 + c * 8 + tid]);
            if (lane == 0 && r > 0) {
                unsigned t1 = (unsigned)r * NR;
                while (ld_acquire(&g_cnt1[repw * 32]) < t1) {}
            }
            __syncwarp();

            const float* h1p = &g_h1rep[repw][(r + 3) & 3][0];   // h1(r-1)
            float p1[8] = {0, 0, 0, 0, 0, 0, 0, 0};
#pragma unroll
            for (int jj = 0; jj < 8; ++jj) {
                float h = __ldcg(&h1p[w * 256 + jj * 32 + lane]);
#pragma unroll
                for (int q = 0; q < 8; ++q) p1[q] += w1r[jj][q] * h;
            }
#pragma unroll
            for (int q = 0; q < 8; ++q)
#pragma unroll
                for (int o = 16; o; o >>= 1) p1[q] += __shfl_xor_sync(~0u, p1[q], o);
            if (lane == 0) {
#pragma unroll
                for (int q = 0; q < 8; ++q) sP1[q * 4 + w] = p1[q];
            }
            asm volatile("bar.sync 1, 128;" ::: "memory");

            if (w == 0) {   // warp 0: WAR gate + finalize + replicate + release
                if (lane == 0 && r >= 4) {   // h2 consumed h1(r-4) -> slot r&3 free
                    unsigned t2 = (unsigned)(r - 3) * NR;
                    while (ld_acquire(&g_cnt2[cpy * 32]) < t2) {}
                }
                __syncwarp();
                float s = 0.f;
                if (lane < 8) {
                    float4 ps = *(const float4*)&sP1[lane * 4];
                    s = u1v + ps.x + ps.y + ps.z + ps.w;
                    s = s > 0.f ? s : 0.01f * s;
                }
                float sv[8];
#pragma unroll
                for (int q = 0; q < 8; ++q) sv[q] = __shfl_sync(~0u, s, q);
                if (lane < NREP) {
                    float* dst = &g_h1rep[lane][r & 3][c * 8];
                    stcg4(dst,     make_float4(sv[0], sv[1], sv[2], sv[3]));
                    stcg4(dst + 4, make_float4(sv[4], sv[5], sv[6], sv[7]));
                    red_release(&g_cnt1[lane * 32], 1u);   // line k covers replica k
                }
            }
        }
    } else {
        // =================== h2 group (warps 4-7) ===================
        int w = (tid >> 5) - 4;
        float w2a[8][4], w2b[4][4];
#pragma unroll
        for (int q = 0; q < 4; ++q) {
            const float* p = W2 + (long)(c * 4 + q) * (HD1 + HD2);
#pragma unroll
            for (int jj = 0; jj < 8; ++jj)
                w2a[jj][q] = p[w * 256 + jj * 32 + lane];
#pragma unroll
            for (int jj = 0; jj < 4; ++jj)
                w2b[jj][q] = p[HD1 + w * 128 + jj * 32 + lane];
        }
        float b2v = 0.f;
        if (w == 0 && lane < 4) b2v = b2[c * 4 + lane];

        for (int r = 1; r <= T_STEPS; ++r) {
            if (tid == 128) {
                unsigned t1 = (unsigned)r * NR;
                while (ld_acquire(&g_cnt1[cpy * 32]) < t1) {}
                if (r > 1) {
                    unsigned t2 = (unsigned)(r - 1) * NR;
                    while (ld_acquire(&g_cnt2[cpy * 32]) < t2) {}
                }
            }
            asm volatile("bar.sync 2, 128;" ::: "memory");

            const float* h1p = &g_h1rep[cpy][(r + 3) & 3][0];   // h1(r-1)
            const float* h2p = &g_h2rep[cpy][(r + 2) & 3][0];   // h2(r-2)
            float p2[4] = {0, 0, 0, 0};
#pragma unroll
            for (int jj = 0; jj < 8; ++jj) {
                float h = __ldcg(&h1p[w * 256 + jj * 32 + lane]);
#pragma unroll
                for (int q = 0; q < 4; ++q) p2[q] += w2a[jj][q] * h;
            }
#pragma unroll
            for (int jj = 0; jj < 4; ++jj) {
                float h = __ldcg(&h2p[w * 128 + jj * 32 + lane]);
#pragma unroll
                for (int q = 0; q < 4; ++q) p2[q] += w2b[jj][q] * h;
            }
#pragma unroll
            for (int q = 0; q < 4; ++q)
#pragma unroll
                for (int o = 16; o; o >>= 1) p2[q] += __shfl_xor_sync(~0u, p2[q], o);
            if (lane == 0) {
#pragma unroll
                for (int q = 0; q < 4; ++q) sP2[q * 4 + w] = p2[q];
            }
            asm volatile("bar.sync 2, 128;" ::: "memory");

            if (w == 0) {   // warp 4: finalize + replicate + release
                float s = 0.f;
                if (lane < 4) {
                    float4 ps = *(const float4*)&sP2[lane * 4];
                    s = b2v + ps.x + ps.y + ps.z + ps.w;
                    s = s > 0.f ? s : 0.01f * s;
                }
                float sv[4];
#pragma unroll
                for (int q = 0; q < 4; ++q) sv[q] = __shfl_sync(~0u, s, q);
                if (lane < NREP) {
                    stcg4(&g_h2rep[lane][(r + 3) & 3][c * 4],
                          make_float4(sv[0], sv[1], sv[2], sv[3]));
                    red_release(&g_cnt2[lane * 32], 1u);
                }
                if (lane == NREP) {   // bf16 copy for logits (read after kernel exit)
                    uint32_t* d = (uint32_t*)&g_h2sb[(r - 1) * HD2 + c * 4];
                    d[0] = pack_bf16(sv[0], sv[1]);
                    d[1] = pack_bf16(sv[2], sv[3]);
                }
            }
        }
    }
}

// ------------------------- logits GEMM (bf16 mma, 4-stage cp.async ring) ---------------
// Dynamic smem: 4 stages x (A 5120 u16 + B 5120 u16) = 81920 B. Issue-ahead 2,
// ONE __syncthreads per K-chunk (stage written at kc+2 was last read at kc-2).
__global__ void __launch_bounds__(256) logits_kernel(const uint16_t* __restrict__ Wb,
                                                     const float* __restrict__ bias,
                                                     float* __restrict__ out,
                                                     int which) {
    extern __shared__ __align__(16) uint16_t dyn[];
    __shared__ float sBias[128];
    __shared__ float sM[128 * 2], sS[128 * 2];

    const int V = which ? VSENS : VGLOB;
    const int pstr = which ? PSTR_S : PSTR_G;
    float* pmax = which ? g_pmaxS : g_pmaxG;
    float* psum = which ? g_psumS : g_psumG;

    int tid = threadIdx.x;
    int m0 = blockIdx.y * 128;
    int n0 = blockIdx.x * 128;
    int lane = tid & 31, warp = tid >> 5;
    int wm = warp & 3, wn = warp >> 2;

    if (tid < 128) {
        int v = n0 + tid;
        sBias[tid] = (v < V) ? bias[v] : 0.f;
    }

    float c[2][8][4];
#pragma unroll
    for (int mt = 0; mt < 2; ++mt)
#pragma unroll
        for (int nt = 0; nt < 8; ++nt)
#pragma unroll
            for (int e = 0; e < 4; ++e) c[mt][nt][e] = 0.f;

    auto issue = [&](int kc) {
        int s = kc & 3;
        uint16_t* sA = dyn + s * 10240;
        uint16_t* sB = sA + 5120;
        int k0 = kc * 32;
#pragma unroll
        for (int p = 0; p < 2; ++p) {
            int f = tid + p * 256;
            int row = f >> 2, seg = f & 3;
            cp_async16(&sA[row * 40 + seg * 8],
                       &g_h2sb[(long)(m0 + row) * HD2 + k0 + seg * 8], 16);
            int vr = n0 + row;
            int srow = vr < V ? vr : 0;
            cp_async16(&sB[row * 40 + seg * 8],
                       &Wb[(long)srow * HD2 + k0 + seg * 8], vr < V ? 16 : 0);
        }
        cp_commit();
    };

    issue(0);
    issue(1);
    for (int kc = 0; kc < 16; ++kc) {
        if (kc + 2 < 16) issue(kc + 2);
        cp_wait<2>();
        __syncthreads();
        const uint16_t* pA = dyn + (kc & 3) * 10240;
        const uint16_t* pB = pA + 5120;
#pragma unroll
        for (int ks = 0; ks < 2; ++ks) {
            int kk = ks * 16;
            uint32_t a[2][4], b[8][2];
            int ar = wm * 32 + (lane >> 2);
            int ac = kk + (lane & 3) * 2;
#pragma unroll
            for (int mt = 0; mt < 2; ++mt) {
                const uint16_t* base = &pA[(ar + mt * 16) * 40 + ac];
                a[mt][0] = *(const uint32_t*)(base);
                a[mt][1] = *(const uint32_t*)(base + 8 * 40);
                a[mt][2] = *(const uint32_t*)(base + 8);
                a[mt][3] = *(const uint32_t*)(base + 8 * 40 + 8);
            }
            int br = wn * 64 + (lane >> 2);
#pragma unroll
            for (int nt = 0; nt < 8; ++nt) {
                const uint16_t* base = &pB[(br + nt * 8) * 40 + ac];
                b[nt][0] = *(const uint32_t*)(base);
                b[nt][1] = *(const uint32_t*)(base + 8);
            }
#pragma unroll
            for (int mt = 0; mt < 2; ++mt)
#pragma unroll
                for (int nt = 0; nt < 8; ++nt) mma_bf16(c[mt][nt], a[mt], b[nt]);
        }
    }
    __syncthreads();

    int rbase = wm * 32 + (lane >> 2);
    int cbase = wn * 64 + (lane & 3) * 2;
#pragma unroll
    for (int mt = 0; mt < 2; ++mt)
#pragma unroll
        for (int h = 0; h < 2; ++h) {
            int rr = rbase + mt * 16 + h * 8;
            long t = m0 + rr;
            float xs[16];
            float M = -CUDART_INF_F;
#pragma unroll
            for (int nt = 0; nt < 8; ++nt)
#pragma unroll
                for (int e = 0; e < 2; ++e) {
                    int cc = cbase + nt * 8 + e;
                    int v = n0 + cc;
                    float x = -CUDART_INF_F;
                    if (v < V) {
                        x = c[mt][nt][h * 2 + e] + sBias[cc];
                        out[t * V + v] = x;
                        M = fmaxf(M, x);
                    }
                    xs[nt * 2 + e] = x;
                }
            float S = 0.f;
#pragma unroll
            for (int i = 0; i < 16; ++i)
                if (xs[i] != -CUDART_INF_F) S += __expf(xs[i] - M);
#pragma unroll
            for (int o = 1; o <= 2; o <<= 1) {
                float m2 = __shfl_xor_sync(~0u, M, o);
                float s2 = __shfl_xor_sync(~0u, S, o);
                lse_merge(M, S, m2, s2);
            }
            if ((lane & 3) == 0) { sM[rr * 2 + wn] = M; sS[rr * 2 + wn] = S; }
        }
    __syncthreads();
    if (tid < 128) {
        float M = sM[tid * 2], S = sS[tid * 2];
        lse_merge(M, S, sM[tid * 2 + 1], sS[tid * 2 + 1]);
        long t = m0 + tid;
        pmax[t * pstr + blockIdx.x] = M;
        psum[t * pstr + blockIdx.x] = S;
    }
}

// ------------------------- per-row LSE reduction -------------------------
__global__ void lse_kernel() {
    int t = blockIdx.x;
    int which = blockIdx.y;
    const float* pm = which ? g_pmaxS : g_pmaxG;
    const float* ps = which ? g_psumS : g_psumG;
    int nb = which ? TILES_S : TILES_G;
    int pstr = which ? PSTR_S : PSTR_G;
    float M = -CUDART_INF_F, S = 0.f;
    for (int i = threadIdx.x; i < nb; i += 128)
        lse_merge(M, S, pm[(long)t * pstr + i], ps[(long)t * pstr + i]);
#pragma unroll
    for (int o = 16; o; o >>= 1) {
        float m2 = __shfl_xor_sync(~0u, M, o);
        float s2 = __shfl_xor_sync(~0u, S, o);
        lse_merge(M, S, m2, s2);
    }
    __shared__ float sm_[4], ss_[4];
    int w = threadIdx.x >> 5;
    if ((threadIdx.x & 31) == 0) { sm_[w] = M; ss_[w] = S; }
    __syncthreads();
    if (threadIdx.x == 0) {
        for (int k = 1; k < 4; ++k) lse_merge(M, S, sm_[k], ss_[k]);
        float lse = M + logf(S);
        if (which) g_lseS[t] = lse; else g_lseG[t] = lse;
    }
}

// ------------------------- in-place logp = logit - lse (row from blockIdx.y) -------------
__global__ void sub_kernel(float* __restrict__ base, int which, int V) {
    int t = blockIdx.y;
    float l = (which ? g_lseS : g_lseG)[t];
    float4* row = (float4*)(base + (size_t)t * V);
    int n4 = V >> 2;
    for (int i = blockIdx.x * blockDim.x + threadIdx.x; i < n4; i += gridDim.x * blockDim.x) {
        float4 v = row[i];
        v.x -= l; v.y -= l; v.z -= l; v.w -= l;
        row[i] = v;
    }
}

// ------------------------- launcher -------------------------
extern "C" void kernel_launch(void* const* d_in, const int* in_sizes, int n_in,
                              void* d_out, int out_size) {
    const float* X  = (const float*)d_in[0];
    const float* W1 = (const float*)d_in[1];
    const float* b1 = (const float*)d_in[2];
    const float* W2 = (const float*)d_in[3];
    const float* b2 = (const float*)d_in[4];
    const float* Wg = (const float*)d_in[5];
    const float* bg = (const float*)d_in[6];
    const float* Ws = (const float*)d_in[7];
    const float* bs = (const float*)d_in[8];
    const int*  idx = (const int*)d_in[9];
    float* outG = (float*)d_out;
    float* outS = outG + (size_t)T_STEPS * VGLOB;

    uint16_t* wgb; cudaGetSymbolAddress((void**)&wgb, g_Wgb);
    uint16_t* wsb; cudaGetSymbolAddress((void**)&wsb, g_Wsb);

    const int LOGITS_SMEM = 4 * 10240 * 2;   // 81920 B dynamic
    cudaFuncSetAttribute(logits_kernel, cudaFuncAttributeMaxDynamicSharedMemorySize, LOGITS_SMEM);

    // rnn_kernel deliberately placed as the 4th launch (ncu pins launch #4)
    init_kernel<<<64, 256>>>();
    u1_kernel<<<dim3(16, 16), 256>>>(X, W1, b1, idx);
    convert_kernel<<<2048, 256>>>(Wg, wgb, VGLOB * HD2 / 4);
    rnn_kernel<<<NR, 256>>>(W1, W2, b2);
    convert_kernel<<<2048, 256>>>(Ws, wsb, VSENS * HD2 / 4);
    logits_kernel<<<dim3(TILES_G, 8), 256, LOGITS_SMEM>>>(wgb, bg, outG, 0);
    logits_kernel<<<dim3(TILES_S, 8), 256, LOGITS_SMEM>>>(wsb, bs, outS, 1);
    lse_kernel<<<dim3(T_STEPS, 2), 128>>>();
    sub_kernel<<<dim3(49, T_STEPS), 256>>>(outG, 0, VGLOB);
    sub_kernel<<<dim3(25, T_STEPS), 256>>>(outS, 1, VSENS);
}

// round 13
// speedup vs baseline: 3.4952x; 3.4952x over previous
#include <cuda_runtime.h>
#include <cuda_bf16.h>
#include <cstdint>
#include <math_constants.h>

#define T_STEPS 1024
#define DIM     300
#define HD1     1024
#define HD2     512
#define VGLOB   50000
#define VSENS   25000
#define NR      128          // rnn CTAs: 1024 = 128*8, 512 = 128*4

#define TILES_G 391
#define TILES_S 196
#define PSTR_G  392
#define PSTR_S  200

// ------------------------- device scratch -------------------------
__device__ __align__(16) float g_U1[T_STEPS * HD1];
__device__ __align__(16) float g_h1rep[8][4][HD1];   // [copy][parity r&3][HD1]
__device__ __align__(16) float g_h2rep[8][2][HD2];   // [copy][parity][HD2]
__device__ __align__(128) unsigned g_cnt1[8 * 32];   // 8 counter lines, 128B apart
__device__ __align__(128) unsigned g_cnt2[8 * 32];
__device__ float g_pmaxG[T_STEPS * PSTR_G];
__device__ float g_psumG[T_STEPS * PSTR_G];
__device__ float g_pmaxS[T_STEPS * PSTR_S];
__device__ float g_psumS[T_STEPS * PSTR_S];
__device__ float g_lseG[T_STEPS];
__device__ float g_lseS[T_STEPS];
// bf16 operands for the logits GEMM
__device__ __align__(16) uint16_t g_h2sb[T_STEPS * HD2];
__device__ __align__(16) uint16_t g_Wgb[(size_t)VGLOB * HD2];
__device__ __align__(16) uint16_t g_Wsb[(size_t)VSENS * HD2];

// ------------------------- helpers -------------------------
__device__ __forceinline__ void red_release(unsigned* p, unsigned v) {
    asm volatile("red.release.gpu.global.add.u32 [%0], %1;" :: "l"(p), "r"(v) : "memory");
}
__device__ __forceinline__ unsigned ld_acquire(const unsigned* p) {
    unsigned v;
    asm volatile("ld.acquire.gpu.global.u32 %0, [%1];" : "=r"(v) : "l"(p) : "memory");
    return v;
}
__device__ __forceinline__ void stcg4(float* p, float4 v) {
    asm volatile("st.global.cg.v4.f32 [%0], {%1,%2,%3,%4};"
                 :: "l"(p), "f"(v.x), "f"(v.y), "f"(v.z), "f"(v.w) : "memory");
}

__device__ __forceinline__ void mma_bf16(float c[4], const uint32_t a[4], const uint32_t b[2]) {
    asm volatile(
        "mma.sync.aligned.m16n8k16.row.col.f32.bf16.bf16.f32 "
        "{%0,%1,%2,%3}, {%4,%5,%6,%7}, {%8,%9}, {%0,%1,%2,%3};"
        : "+f"(c[0]), "+f"(c[1]), "+f"(c[2]), "+f"(c[3])
        : "r"(a[0]), "r"(a[1]), "r"(a[2]), "r"(a[3]), "r"(b[0]), "r"(b[1]));
}

__device__ __forceinline__ void cp_async16(void* dst_smem, const void* src, int src_bytes) {
    uint32_t d = (uint32_t)__cvta_generic_to_shared(dst_smem);
    asm volatile("cp.async.cg.shared.global [%0], [%1], 16, %2;"
                 :: "r"(d), "l"(src), "r"(src_bytes));
}
__device__ __forceinline__ void cp_commit() { asm volatile("cp.async.commit_group;"); }
template <int N>
__device__ __forceinline__ void cp_wait() { asm volatile("cp.async.wait_group %0;" :: "n"(N)); }

__device__ __forceinline__ void lse_merge(float& M, float& S, float m, float s) {
    float nm = fmaxf(M, m);
    if (nm == -CUDART_INF_F) { M = nm; S = 0.f; return; }
    S = S * __expf(M - nm) + s * __expf(m - nm);
    M = nm;
}

__device__ __forceinline__ uint32_t pack_bf16(float a, float b) {
    __nv_bfloat16 ba = __float2bfloat16(a), bb = __float2bfloat16(b);
    return (uint32_t)reinterpret_cast<unsigned short&>(ba) |
           ((uint32_t)reinterpret_cast<unsigned short&>(bb) << 16);
}

// ------------------------- init -------------------------
__global__ void init_kernel() {
    int tid = threadIdx.x + blockIdx.x * blockDim.x;
    int stride = gridDim.x * blockDim.x;
    if (tid < 8 * 32) { g_cnt1[tid] = 0u; g_cnt2[tid] = 0u; }
    for (int i = tid; i < 8 * 4 * HD1; i += stride) ((float*)g_h1rep)[i] = 0.f;
    for (int i = tid; i < 8 * 2 * HD2; i += stride) ((float*)g_h2rep)[i] = 0.f;
}

// ------------------------- fp32 -> bf16 weight conversion -------------------------
__global__ void convert_kernel(const float* __restrict__ src, uint16_t* __restrict__ dst, int n4) {
    int i = blockIdx.x * blockDim.x + threadIdx.x;
    int stride = gridDim.x * blockDim.x;
    uint32_t* d32 = (uint32_t*)dst;
    const float4* s4 = (const float4*)src;
    for (; i < n4; i += stride) {
        float4 v = s4[i];
        d32[2 * i]     = pack_bf16(v.x, v.y);
        d32[2 * i + 1] = pack_bf16(v.z, v.w);
    }
}

// ------------------------- U1 = E @ W1e^T + b1 -------------------------
__global__ void __launch_bounds__(256) u1_kernel(const float* __restrict__ X,
                                                 const float* __restrict__ W1,
                                                 const float* __restrict__ b1,
                                                 const int* __restrict__ idx) {
    __shared__ float sA[20][64];
    __shared__ float sB[20][64];
    __shared__ int sidx[64];
    int tid = threadIdx.x;
    int t0 = blockIdx.y * 64, i0 = blockIdx.x * 64;
    if (tid < 64) sidx[tid] = idx[t0 + tid];
    __syncthreads();
    float acc[4][4];
#pragma unroll
    for (int a = 0; a < 4; ++a)
#pragma unroll
        for (int b = 0; b < 4; ++b) acc[a][b] = 0.f;
    int tx = tid & 15, ty = tid >> 4;
    for (int kc = 0; kc < 15; ++kc) {
        int k0 = kc * 20;
        for (int i = tid; i < 1280; i += 256) {
            int k = i >> 6, m = i & 63;
            sA[k][m] = X[(long)sidx[m] * DIM + k0 + k];
            sB[k][m] = W1[(long)(i0 + m) * (DIM + HD1) + k0 + k];
        }
        __syncthreads();
#pragma unroll
        for (int k = 0; k < 20; ++k) {
            float a[4], b[4];
#pragma unroll
            for (int e = 0; e < 4; ++e) { a[e] = sA[k][ty * 4 + e]; b[e] = sB[k][tx * 4 + e]; }
#pragma unroll
            for (int ii = 0; ii < 4; ++ii)
#pragma unroll
                for (int jj = 0; jj < 4; ++jj) acc[ii][jj] += a[ii] * b[jj];
        }
        __syncthreads();
    }
#pragma unroll
    for (int ii = 0; ii < 4; ++ii)
#pragma unroll
        for (int jj = 0; jj < 4; ++jj) {
            int t = t0 + ty * 4 + ii, n = i0 + tx * 4 + jj;
            g_U1[t * HD1 + n] = acc[ii][jj] + b1[n];
        }
}

// ------------------------- persistent RNN core (warp-specialized, 128 CTAs) ----------
// EXACT round-8 measured-best structure. Warps 0-3: h1 chain (quad-buffered,
// parity r&3; WAR gate = lagged cnt2 polled at TOP of round by tid 0, overlapping
// the cnt1 wait). Warps 4-7: h2 chain (double-buffered, shadowed). 8 replicas;
// writer warp-0/4 lane k stores replica k then red.release counter line k;
// each CTA polls only line c&7.
__global__ void __launch_bounds__(256) rnn_kernel(const float* __restrict__ W1,
                                                  const float* __restrict__ W2,
                                                  const float* __restrict__ b2) {
    __shared__ __align__(16) float sP1[32];   // [q 0..7][warp 0..3]
    __shared__ __align__(16) float sP2[16];   // [q 0..3][warp 0..3]
    int tid = threadIdx.x, c = blockIdx.x;
    int lane = tid & 31;
    int cpy = c & 7;

    if (tid < 128) {
        // =================== h1 group (warps 0-3) ===================
        int w = tid >> 5;
        float w1r[8][8];   // [jj][q]
#pragma unroll
        for (int q = 0; q < 8; ++q) {
            const float* p = W1 + (long)(c * 8 + q) * (DIM + HD1) + DIM;
#pragma unroll
            for (int jj = 0; jj < 8; ++jj)
                w1r[jj][q] = p[w * 256 + jj * 32 + lane];
        }

        for (int r = 0; r < T_STEPS; ++r) {
            float u1v = 0.f;
            if (tid < 8) u1v = __ldg(&g_U1[r * HD1 + c * 8 + tid]);
            if (tid == 0) {
                // WAR gate first (usually satisfied), then the h1 chain wait
                if (r >= 4) {
                    unsigned t2 = (unsigned)(r - 3) * NR;
                    while (ld_acquire(&g_cnt2[cpy * 32]) < t2) {}
                }
                if (r > 0) {
                    unsigned t1 = (unsigned)r * NR;
                    while (ld_acquire(&g_cnt1[cpy * 32]) < t1) {}
                }
            }
            asm volatile("bar.sync 1, 128;" ::: "memory");

            const float* h1p = g_h1rep[cpy][(r + 3) & 3];   // h1(r-1)
            float p1[8] = {0, 0, 0, 0, 0, 0, 0, 0};
#pragma unroll
            for (int jj = 0; jj < 8; ++jj) {
                float h = __ldcg(&h1p[w * 256 + jj * 32 + lane]);
#pragma unroll
                for (int q = 0; q < 8; ++q) p1[q] += w1r[jj][q] * h;
            }
#pragma unroll
            for (int q = 0; q < 8; ++q)
#pragma unroll
                for (int o = 16; o; o >>= 1) p1[q] += __shfl_xor_sync(~0u, p1[q], o);
            if (lane == 0) {
#pragma unroll
                for (int q = 0; q < 8; ++q) sP1[q * 4 + w] = p1[q];
            }
            asm volatile("bar.sync 1, 128;" ::: "memory");

            if (w == 0) {   // warp 0: finalize + replicate + release
                float s = 0.f;
                if (lane < 8) {
                    float4 ps = *(const float4*)&sP1[lane * 4];
                    s = u1v + ps.x + ps.y + ps.z + ps.w;
                    s = s > 0.f ? s : 0.01f * s;
                }
                float sv[8];
#pragma unroll
                for (int q = 0; q < 8; ++q) sv[q] = __shfl_sync(~0u, s, q);
                if (lane < 8) {
                    float* dst = &g_h1rep[lane][r & 3][c * 8];
                    stcg4(dst,     make_float4(sv[0], sv[1], sv[2], sv[3]));
                    stcg4(dst + 4, make_float4(sv[4], sv[5], sv[6], sv[7]));
                    red_release(&g_cnt1[lane * 32], 1u);   // line 'lane' covers replica 'lane'
                }
            }
        }
    } else {
        // =================== h2 group (warps 4-7) ===================
        int w = (tid >> 5) - 4;
        float w2a[8][4], w2b[4][4];
#pragma unroll
        for (int q = 0; q < 4; ++q) {
            const float* p = W2 + (long)(c * 4 + q) * (HD1 + HD2);
#pragma unroll
            for (int jj = 0; jj < 8; ++jj)
                w2a[jj][q] = p[w * 256 + jj * 32 + lane];
#pragma unroll
            for (int jj = 0; jj < 4; ++jj)
                w2b[jj][q] = p[HD1 + w * 128 + jj * 32 + lane];
        }
        float b2v = 0.f;
        if (tid >= 128 && tid < 132) b2v = b2[c * 4 + (tid - 128)];

        for (int r = 1; r <= T_STEPS; ++r) {
            if (tid == 128) {
                unsigned t1 = (unsigned)r * NR;
                while (ld_acquire(&g_cnt1[cpy * 32]) < t1) {}
                if (r > 1) {
                    unsigned t2 = (unsigned)(r - 1) * NR;
                    while (ld_acquire(&g_cnt2[cpy * 32]) < t2) {}
                }
            }
            asm volatile("bar.sync 2, 128;" ::: "memory");

            const float* h1p = g_h1rep[cpy][(r + 3) & 3];   // h1(r-1)
            const float* h2p = g_h2rep[cpy][r & 1];          // h2(r-2)
            float p2[4] = {0, 0, 0, 0};
#pragma unroll
            for (int jj = 0; jj < 8; ++jj) {
                float h = __ldcg(&h1p[w * 256 + jj * 32 + lane]);
#pragma unroll
                for (int q = 0; q < 4; ++q) p2[q] += w2a[jj][q] * h;
            }
#pragma unroll
            for (int jj = 0; jj < 4; ++jj) {
                float h = __ldcg(&h2p[w * 128 + jj * 32 + lane]);
#pragma unroll
                for (int q = 0; q < 4; ++q) p2[q] += w2b[jj][q] * h;
            }
#pragma unroll
            for (int q = 0; q < 4; ++q)
#pragma unroll
                for (int o = 16; o; o >>= 1) p2[q] += __shfl_xor_sync(~0u, p2[q], o);
            if (lane == 0) {
#pragma unroll
                for (int q = 0; q < 4; ++q) sP2[q * 4 + w] = p2[q];
            }
            asm volatile("bar.sync 2, 128;" ::: "memory");

            if (w == 0) {   // warp 4: finalize + replicate + release
                float s = 0.f;
                if (lane < 4) {
                    float4 ps = *(const float4*)&sP2[lane * 4];
                    s = b2v + ps.x + ps.y + ps.z + ps.w;
                    s = s > 0.f ? s : 0.01f * s;
                }
                float sv[4];
#pragma unroll
                for (int q = 0; q < 4; ++q) sv[q] = __shfl_sync(~0u, s, q);
                if (lane < 8) {
                    stcg4(&g_h2rep[lane][(r + 1) & 1][c * 4],
                          make_float4(sv[0], sv[1], sv[2], sv[3]));
                    red_release(&g_cnt2[lane * 32], 1u);
                }
                if (lane == 8) {   // bf16 copy for logits (read after kernel exit)
                    uint32_t* d = (uint32_t*)&g_h2sb[(r - 1) * HD2 + c * 4];
                    d[0] = pack_bf16(sv[0], sv[1]);
                    d[1] = pack_bf16(sv[2], sv[3]);
                }
            }
        }
    }
}

// ------------------------- logits GEMM (bf16 mma, cp.async pipelined) -------------------------
__global__ void __launch_bounds__(256) logits_kernel(const uint16_t* __restrict__ Wb,
                                                     const float* __restrict__ bias,
                                                     float* __restrict__ out,
                                                     int which) {
    __shared__ __align__(16) uint16_t sA[2][128 * 40];
    __shared__ __align__(16) uint16_t sB[2][128 * 40];
    __shared__ float sBias[128];
    __shared__ float sM[128 * 2], sS[128 * 2];

    const int V = which ? VSENS : VGLOB;
    const int pstr = which ? PSTR_S : PSTR_G;
    float* pmax = which ? g_pmaxS : g_pmaxG;
    float* psum = which ? g_psumS : g_psumG;

    int tid = threadIdx.x;
    int m0 = blockIdx.y * 128;
    int n0 = blockIdx.x * 128;
    int lane = tid & 31, warp = tid >> 5;
    int wm = warp & 3, wn = warp >> 2;

    if (tid < 128) {
        int v = n0 + tid;
        sBias[tid] = (v < V) ? bias[v] : 0.f;
    }

    float c[2][8][4];
#pragma unroll
    for (int mt = 0; mt < 2; ++mt)
#pragma unroll
        for (int nt = 0; nt < 8; ++nt)
#pragma unroll
            for (int e = 0; e < 4; ++e) c[mt][nt][e] = 0.f;

    auto issue = [&](int kc, int s) {
        int k0 = kc * 32;
#pragma unroll
        for (int p = 0; p < 2; ++p) {
            int f = tid + p * 256;
            int row = f >> 2, seg = f & 3;
            cp_async16(&sA[s][row * 40 + seg * 8],
                       &g_h2sb[(long)(m0 + row) * HD2 + k0 + seg * 8], 16);
            int vr = n0 + row;
            int srow = vr < V ? vr : 0;
            cp_async16(&sB[s][row * 40 + seg * 8],
                       &Wb[(long)srow * HD2 + k0 + seg * 8], vr < V ? 16 : 0);
        }
        cp_commit();
    };

    issue(0, 0);
    for (int kc = 0; kc < 16; ++kc) {
        if (kc + 1 < 16) { issue(kc + 1, (kc + 1) & 1); cp_wait<1>(); }
        else             { cp_wait<0>(); }
        __syncthreads();
        const uint16_t* pA = sA[kc & 1];
        const uint16_t* pB = sB[kc & 1];
#pragma unroll
        for (int ks = 0; ks < 2; ++ks) {
            int kk = ks * 16;
            uint32_t a[2][4], b[8][2];
            int ar = wm * 32 + (lane >> 2);
            int ac = kk + (lane & 3) * 2;
#pragma unroll
            for (int mt = 0; mt < 2; ++mt) {
                const uint16_t* base = &pA[(ar + mt * 16) * 40 + ac];
                a[mt][0] = *(const uint32_t*)(base);
                a[mt][1] = *(const uint32_t*)(base + 8 * 40);
                a[mt][2] = *(const uint32_t*)(base + 8);
                a[mt][3] = *(const uint32_t*)(base + 8 * 40 + 8);
            }
            int br = wn * 64 + (lane >> 2);
#pragma unroll
            for (int nt = 0; nt < 8; ++nt) {
                const uint16_t* base = &pB[(br + nt * 8) * 40 + ac];
                b[nt][0] = *(const uint32_t*)(base);
                b[nt][1] = *(const uint32_t*)(base + 8);
            }
#pragma unroll
            for (int mt = 0; mt < 2; ++mt)
#pragma unroll
                for (int nt = 0; nt < 8; ++nt) mma_bf16(c[mt][nt], a[mt], b[nt]);
        }
        __syncthreads();
    }

    int rbase = wm * 32 + (lane >> 2);
    int cbase = wn * 64 + (lane & 3) * 2;
#pragma unroll
    for (int mt = 0; mt < 2; ++mt)
#pragma unroll
        for (int h = 0; h < 2; ++h) {
            int rr = rbase + mt * 16 + h * 8;
            long t = m0 + rr;
            float xs[16];
            float M = -CUDART_INF_F;
#pragma unroll
            for (int nt = 0; nt < 8; ++nt)
#pragma unroll
                for (int e = 0; e < 2; ++e) {
                    int cc = cbase + nt * 8 + e;
                    int v = n0 + cc;
                    float x = -CUDART_INF_F;
                    if (v < V) {
                        x = c[mt][nt][h * 2 + e] + sBias[cc];
                        out[t * V + v] = x;
                        M = fmaxf(M, x);
                    }
                    xs[nt * 2 + e] = x;
                }
            float S = 0.f;
#pragma unroll
            for (int i = 0; i < 16; ++i)
                if (xs[i] != -CUDART_INF_F) S += __expf(xs[i] - M);
#pragma unroll
            for (int o = 1; o <= 2; o <<= 1) {
                float m2 = __shfl_xor_sync(~0u, M, o);
                float s2 = __shfl_xor_sync(~0u, S, o);
                lse_merge(M, S, m2, s2);
            }
            if ((lane & 3) == 0) { sM[rr * 2 + wn] = M; sS[rr * 2 + wn] = S; }
        }
    __syncthreads();
    if (tid < 128) {
        float M = sM[tid * 2], S = sS[tid * 2];
        lse_merge(M, S, sM[tid * 2 + 1], sS[tid * 2 + 1]);
        long t = m0 + tid;
        pmax[t * pstr + blockIdx.x] = M;
        psum[t * pstr + blockIdx.x] = S;
    }
}

// ------------------------- per-row LSE reduction -------------------------
__global__ void lse_kernel() {
    int t = blockIdx.x;
    int which = blockIdx.y;
    const float* pm = which ? g_pmaxS : g_pmaxG;
    const float* ps = which ? g_psumS : g_psumG;
    int nb = which ? TILES_S : TILES_G;
    int pstr = which ? PSTR_S : PSTR_G;
    float M = -CUDART_INF_F, S = 0.f;
    for (int i = threadIdx.x; i < nb; i += 128)
        lse_merge(M, S, pm[(long)t * pstr + i], ps[(long)t * pstr + i]);
#pragma unroll
    for (int o = 16; o; o >>= 1) {
        float m2 = __shfl_xor_sync(~0u, M, o);
        float s2 = __shfl_xor_sync(~0u, S, o);
        lse_merge(M, S, m2, s2);
    }
    __shared__ float sm_[4], ss_[4];
    int w = threadIdx.x >> 5;
    if ((threadIdx.x & 31) == 0) { sm_[w] = M; ss_[w] = S; }
    __syncthreads();
    if (threadIdx.x == 0) {
        for (int k = 1; k < 4; ++k) lse_merge(M, S, sm_[k], ss_[k]);
        float lse = M + logf(S);
        if (which) g_lseS[t] = lse; else g_lseG[t] = lse;
    }
}

// ------------------------- in-place logp = logit - lse (row from blockIdx.y) -------------
__global__ void sub_kernel(float* __restrict__ base, int which, int V) {
    int t = blockIdx.y;
    float l = (which ? g_lseS : g_lseG)[t];
    float4* row = (float4*)(base + (size_t)t * V);
    int n4 = V >> 2;
    for (int i = blockIdx.x * blockDim.x + threadIdx.x; i < n4; i += gridDim.x * blockDim.x) {
        float4 v = row[i];
        v.x -= l; v.y -= l; v.z -= l; v.w -= l;
        row[i] = v;
    }
}

// ------------------------- launcher -------------------------
extern "C" void kernel_launch(void* const* d_in, const int* in_sizes, int n_in,
                              void* d_out, int out_size) {
    const float* X  = (const float*)d_in[0];
    const float* W1 = (const float*)d_in[1];
    const float* b1 = (const float*)d_in[2];
    const float* W2 = (const float*)d_in[3];
    const float* b2 = (const float*)d_in[4];
    const float* Wg = (const float*)d_in[5];
    const float* bg = (const float*)d_in[6];
    const float* Ws = (const float*)d_in[7];
    const float* bs = (const float*)d_in[8];
    const int*  idx = (const int*)d_in[9];
    float* outG = (float*)d_out;
    float* outS = outG + (size_t)T_STEPS * VGLOB;

    uint16_t* wgb; cudaGetSymbolAddress((void**)&wgb, g_Wgb);
    uint16_t* wsb; cudaGetSymbolAddress((void**)&wsb, g_Wsb);

    // rnn_kernel deliberately placed as the 4th launch (ncu pins launch #4)
    init_kernel<<<64, 256>>>();
    u1_kernel<<<dim3(16, 16), 256>>>(X, W1, b1, idx);
    convert_kernel<<<2048, 256>>>(Wg, wgb, VGLOB * HD2 / 4);
    rnn_kernel<<<NR, 256>>>(W1, W2, b2);
    convert_kernel<<<2048, 256>>>(Ws, wsb, VSENS * HD2 / 4);
    logits_kernel<<<dim3(TILES_G, 8), 256>>>(wgb, bg, outG, 0);
    logits_kernel<<<dim3(TILES_S, 8), 256>>>(wsb, bs, outS, 1);
    lse_kernel<<<dim3(T_STEPS, 2), 128>>>();
    sub_kernel<<<dim3(49, T_STEPS), 256>>>(outG, 0, VGLOB);
    sub_kernel<<<dim3(25, T_STEPS), 256>>>(outS, 1, VSENS);
}

// round 14
// speedup vs baseline: 3.6082x; 1.0323x over previous
#include <cuda_runtime.h>
#include <cuda_bf16.h>
#include <cstdint>
#include <math_constants.h>

#define T_STEPS 1024
#define DIM     300
#define HD1     1024
#define HD2     512
#define VGLOB   50000
#define VSENS   25000
#define NR      128          // rnn CTAs: 1024 = 128*8, 512 = 128*4

#define TILES_G 391
#define TILES_S 196
#define TPB     (TILES_G + TILES_S)   // 587 tiles per m-block
#define NTILES  (8 * TPB)             // 4696
#define PSTR_G  392
#define PSTR_S  200

// ------------------------- device scratch -------------------------
__device__ __align__(16) float g_U1[T_STEPS * HD1];
__device__ __align__(16) float g_h1rep[8][4][HD1];   // [copy][parity r&3][HD1]
__device__ __align__(16) float g_h2rep[8][2][HD2];   // [copy][parity][HD2]
__device__ __align__(128) unsigned g_cnt1[8 * 32];   // 8 counter lines, 128B apart
__device__ __align__(128) unsigned g_cnt2[8 * 32];
__device__ float g_pmaxG[T_STEPS * PSTR_G];
__device__ float g_psumG[T_STEPS * PSTR_G];
__device__ float g_pmaxS[T_STEPS * PSTR_S];
__device__ float g_psumS[T_STEPS * PSTR_S];
__device__ float g_lseG[T_STEPS];
__device__ float g_lseS[T_STEPS];
// bf16 operands for the logits GEMM
__device__ __align__(16) uint16_t g_h2sb[T_STEPS * HD2];
__device__ __align__(16) uint16_t g_Wgb[(size_t)VGLOB * HD2];
__device__ __align__(16) uint16_t g_Wsb[(size_t)VSENS * HD2];

// ------------------------- helpers -------------------------
__device__ __forceinline__ void red_release(unsigned* p, unsigned v) {
    asm volatile("red.release.gpu.global.add.u32 [%0], %1;" :: "l"(p), "r"(v) : "memory");
}
__device__ __forceinline__ unsigned ld_acquire(const unsigned* p) {
    unsigned v;
    asm volatile("ld.acquire.gpu.global.u32 %0, [%1];" : "=r"(v) : "l"(p) : "memory");
    return v;
}
__device__ __forceinline__ void stcg4(float* p, float4 v) {
    asm volatile("st.global.cg.v4.f32 [%0], {%1,%2,%3,%4};"
                 :: "l"(p), "f"(v.x), "f"(v.y), "f"(v.z), "f"(v.w) : "memory");
}

__device__ __forceinline__ void mma_bf16(float c[4], const uint32_t a[4], const uint32_t b[2]) {
    asm volatile(
        "mma.sync.aligned.m16n8k16.row.col.f32.bf16.bf16.f32 "
        "{%0,%1,%2,%3}, {%4,%5,%6,%7}, {%8,%9}, {%0,%1,%2,%3};"
        : "+f"(c[0]), "+f"(c[1]), "+f"(c[2]), "+f"(c[3])
        : "r"(a[0]), "r"(a[1]), "r"(a[2]), "r"(a[3]), "r"(b[0]), "r"(b[1]));
}

__device__ __forceinline__ void cp_async16(void* dst_smem, const void* src, int src_bytes) {
    uint32_t d = (uint32_t)__cvta_generic_to_shared(dst_smem);
    asm volatile("cp.async.cg.shared.global [%0], [%1], 16, %2;"
                 :: "r"(d), "l"(src), "r"(src_bytes));
}
__device__ __forceinline__ void cp_commit() { asm volatile("cp.async.commit_group;"); }
template <int N>
__device__ __forceinline__ void cp_wait() { asm volatile("cp.async.wait_group %0;" :: "n"(N)); }

__device__ __forceinline__ void lse_merge(float& M, float& S, float m, float s) {
    float nm = fmaxf(M, m);
    if (nm == -CUDART_INF_F) { M = nm; S = 0.f; return; }
    S = S * __expf(M - nm) + s * __expf(m - nm);
    M = nm;
}

__device__ __forceinline__ uint32_t pack_bf16(float a, float b) {
    __nv_bfloat16 ba = __float2bfloat16(a), bb = __float2bfloat16(b);
    return (uint32_t)reinterpret_cast<unsigned short&>(ba) |
           ((uint32_t)reinterpret_cast<unsigned short&>(bb) << 16);
}

// ------------------------- init -------------------------
__global__ void init_kernel() {
    int tid = threadIdx.x + blockIdx.x * blockDim.x;
    int stride = gridDim.x * blockDim.x;
    if (tid < 8 * 32) { g_cnt1[tid] = 0u; g_cnt2[tid] = 0u; }
    for (int i = tid; i < 8 * 4 * HD1; i += stride) ((float*)g_h1rep)[i] = 0.f;
    for (int i = tid; i < 8 * 2 * HD2; i += stride) ((float*)g_h2rep)[i] = 0.f;
}

// ------------------------- fp32 -> bf16 weight conversion -------------------------
__global__ void convert_kernel(const float* __restrict__ src, uint16_t* __restrict__ dst, int n4) {
    int i = blockIdx.x * blockDim.x + threadIdx.x;
    int stride = gridDim.x * blockDim.x;
    uint32_t* d32 = (uint32_t*)dst;
    const float4* s4 = (const float4*)src;
    for (; i < n4; i += stride) {
        float4 v = s4[i];
        d32[2 * i]     = pack_bf16(v.x, v.y);
        d32[2 * i + 1] = pack_bf16(v.z, v.w);
    }
}

// ------------------------- U1 = E @ W1e^T + b1 -------------------------
__global__ void __launch_bounds__(256) u1_kernel(const float* __restrict__ X,
                                                 const float* __restrict__ W1,
                                                 const float* __restrict__ b1,
                                                 const int* __restrict__ idx) {
    __shared__ float sA[20][64];
    __shared__ float sB[20][64];
    __shared__ int sidx[64];
    int tid = threadIdx.x;
    int t0 = blockIdx.y * 64, i0 = blockIdx.x * 64;
    if (tid < 64) sidx[tid] = idx[t0 + tid];
    __syncthreads();
    float acc[4][4];
#pragma unroll
    for (int a = 0; a < 4; ++a)
#pragma unroll
        for (int b = 0; b < 4; ++b) acc[a][b] = 0.f;
    int tx = tid & 15, ty = tid >> 4;
    for (int kc = 0; kc < 15; ++kc) {
        int k0 = kc * 20;
        for (int i = tid; i < 1280; i += 256) {
            int k = i >> 6, m = i & 63;
            sA[k][m] = X[(long)sidx[m] * DIM + k0 + k];
            sB[k][m] = W1[(long)(i0 + m) * (DIM + HD1) + k0 + k];
        }
        __syncthreads();
#pragma unroll
        for (int k = 0; k < 20; ++k) {
            float a[4], b[4];
#pragma unroll
            for (int e = 0; e < 4; ++e) { a[e] = sA[k][ty * 4 + e]; b[e] = sB[k][tx * 4 + e]; }
#pragma unroll
            for (int ii = 0; ii < 4; ++ii)
#pragma unroll
                for (int jj = 0; jj < 4; ++jj) acc[ii][jj] += a[ii] * b[jj];
        }
        __syncthreads();
    }
#pragma unroll
    for (int ii = 0; ii < 4; ++ii)
#pragma unroll
        for (int jj = 0; jj < 4; ++jj) {
            int t = t0 + ty * 4 + ii, n = i0 + tx * 4 + jj;
            g_U1[t * HD1 + n] = acc[ii][jj] + b1[n];
        }
}

// ------------------------- fused RNN + logits kernel (512 threads) -------------------
// Warps 0-3: h1 chain (exact round-13 code, bar 1). Warps 4-7: h2 chain (bar 2;
// h2sb bf16 row stored by the SAME lanes that release cnt2 -> acquire chain is
// per-thread correct for in-kernel consumers). Warps 8-15: logits tile workers
// (bar 3): static tile schedule (CTA c: tiles c, c+128, ...), ordered by m-block;
// each tile gated on cnt2 >= (m0+128)*NR before cp.async-reading g_h2sb.
__global__ void __launch_bounds__(512, 1) fused_kernel(const float* __restrict__ W1,
                                                       const float* __restrict__ W2,
                                                       const float* __restrict__ b2,
                                                       const float* __restrict__ bg,
                                                       const float* __restrict__ bs,
                                                       float* __restrict__ outG,
                                                       float* __restrict__ outS) {
    __shared__ __align__(16) float sP1[32];   // [q 0..7][warp 0..3]
    __shared__ __align__(16) float sP2[16];   // [q 0..3][warp 0..3]
    __shared__ __align__(16) uint16_t sA[2][128 * 40];
    __shared__ __align__(16) uint16_t sB[2][128 * 40];
    __shared__ float sBias[128];
    __shared__ float sM[128 * 2], sS_[128 * 2];

    int tid = threadIdx.x, c = blockIdx.x;
    int lane = tid & 31;
    int cpy = c & 7;

    if (tid < 128) {
        // =================== h1 group (warps 0-3) ===================
        int w = tid >> 5;
        float w1r[8][8];   // [jj][q]
#pragma unroll
        for (int q = 0; q < 8; ++q) {
            const float* p = W1 + (long)(c * 8 + q) * (DIM + HD1) + DIM;
#pragma unroll
            for (int jj = 0; jj < 8; ++jj)
                w1r[jj][q] = p[w * 256 + jj * 32 + lane];
        }

        for (int r = 0; r < T_STEPS; ++r) {
            float u1v = 0.f;
            if (tid < 8) u1v = __ldg(&g_U1[r * HD1 + c * 8 + tid]);
            if (tid == 0) {
                if (r >= 4) {   // WAR gate (usually satisfied), overlapping cnt1 wait
                    unsigned t2 = (unsigned)(r - 3) * NR;
                    while (ld_acquire(&g_cnt2[cpy * 32]) < t2) {}
                }
                if (r > 0) {
                    unsigned t1 = (unsigned)r * NR;
                    while (ld_acquire(&g_cnt1[cpy * 32]) < t1) {}
                }
            }
            asm volatile("bar.sync 1, 128;" ::: "memory");

            const float* h1p = g_h1rep[cpy][(r + 3) & 3];   // h1(r-1)
            float p1[8] = {0, 0, 0, 0, 0, 0, 0, 0};
#pragma unroll
            for (int jj = 0; jj < 8; ++jj) {
                float h = __ldcg(&h1p[w * 256 + jj * 32 + lane]);
#pragma unroll
                for (int q = 0; q < 8; ++q) p1[q] += w1r[jj][q] * h;
            }
#pragma unroll
            for (int q = 0; q < 8; ++q)
#pragma unroll
                for (int o = 16; o; o >>= 1) p1[q] += __shfl_xor_sync(~0u, p1[q], o);
            if (lane == 0) {
#pragma unroll
                for (int q = 0; q < 8; ++q) sP1[q * 4 + w] = p1[q];
            }
            asm volatile("bar.sync 1, 128;" ::: "memory");

            if (w == 0) {
                float s = 0.f;
                if (lane < 8) {
                    float4 ps = *(const float4*)&sP1[lane * 4];
                    s = u1v + ps.x + ps.y + ps.z + ps.w;
                    s = s > 0.f ? s : 0.01f * s;
                }
                float sv[8];
#pragma unroll
                for (int q = 0; q < 8; ++q) sv[q] = __shfl_sync(~0u, s, q);
                if (lane < 8) {
                    float* dst = &g_h1rep[lane][r & 3][c * 8];
                    stcg4(dst,     make_float4(sv[0], sv[1], sv[2], sv[3]));
                    stcg4(dst + 4, make_float4(sv[4], sv[5], sv[6], sv[7]));
                    red_release(&g_cnt1[lane * 32], 1u);
                }
            }
        }
    } else if (tid < 256) {
        // =================== h2 group (warps 4-7) ===================
        int w = (tid >> 5) - 4;
        float w2a[8][4], w2b[4][4];
#pragma unroll
        for (int q = 0; q < 4; ++q) {
            const float* p = W2 + (long)(c * 4 + q) * (HD1 + HD2);
#pragma unroll
            for (int jj = 0; jj < 8; ++jj)
                w2a[jj][q] = p[w * 256 + jj * 32 + lane];
#pragma unroll
            for (int jj = 0; jj < 4; ++jj)
                w2b[jj][q] = p[HD1 + w * 128 + jj * 32 + lane];
        }
        float b2v = 0.f;
        if (tid >= 128 && tid < 132) b2v = b2[c * 4 + (tid - 128)];

        for (int r = 1; r <= T_STEPS; ++r) {
            if (tid == 128) {
                unsigned t1 = (unsigned)r * NR;
                while (ld_acquire(&g_cnt1[cpy * 32]) < t1) {}
                if (r > 1) {
                    unsigned t2 = (unsigned)(r - 1) * NR;
                    while (ld_acquire(&g_cnt2[cpy * 32]) < t2) {}
                }
            }
            asm volatile("bar.sync 2, 128;" ::: "memory");

            const float* h1p = g_h1rep[cpy][(r + 3) & 3];   // h1(r-1)
            const float* h2p = g_h2rep[cpy][r & 1];          // h2(r-2)
            float p2[4] = {0, 0, 0, 0};
#pragma unroll
            for (int jj = 0; jj < 8; ++jj) {
                float h = __ldcg(&h1p[w * 256 + jj * 32 + lane]);
#pragma unroll
                for (int q = 0; q < 4; ++q) p2[q] += w2a[jj][q] * h;
            }
#pragma unroll
            for (int jj = 0; jj < 4; ++jj) {
                float h = __ldcg(&h2p[w * 128 + jj * 32 + lane]);
#pragma unroll
                for (int q = 0; q < 4; ++q) p2[q] += w2b[jj][q] * h;
            }
#pragma unroll
            for (int q = 0; q < 4; ++q)
#pragma unroll
                for (int o = 16; o; o >>= 1) p2[q] += __shfl_xor_sync(~0u, p2[q], o);
            if (lane == 0) {
#pragma unroll
                for (int q = 0; q < 4; ++q) sP2[q * 4 + w] = p2[q];
            }
            asm volatile("bar.sync 2, 128;" ::: "memory");

            if (w == 0) {
                float s = 0.f;
                if (lane < 4) {
                    float4 ps = *(const float4*)&sP2[lane * 4];
                    s = b2v + ps.x + ps.y + ps.z + ps.w;
                    s = s > 0.f ? s : 0.01f * s;
                }
                float sv[4];
#pragma unroll
                for (int q = 0; q < 4; ++q) sv[q] = __shfl_sync(~0u, s, q);
                if (lane < 8) {
                    stcg4(&g_h2rep[lane][(r + 1) & 1][c * 4],
                          make_float4(sv[0], sv[1], sv[2], sv[3]));
                    // h2sb row stored by the SAME lanes that release (all 8 lanes,
                    // same 8 bytes) -> in-kernel consumers synchronized via cnt2.
                    unsigned long long hv =
                        (unsigned long long)pack_bf16(sv[0], sv[1]) |
                        ((unsigned long long)pack_bf16(sv[2], sv[3]) << 32);
                    *(unsigned long long*)&g_h2sb[(r - 1) * HD2 + c * 4] = hv;
                    red_release(&g_cnt2[lane * 32], 1u);
                }
            }
        }
    } else {
        // =================== logits tile workers (warps 8-15) ===================
        int ltid = tid - 256;
        int lwarp = ltid >> 5;
        int wm = lwarp & 3, wn = lwarp >> 2;

        for (int tt = c; tt < NTILES; tt += NR) {
            int mblk = tt / TPB, rem = tt % TPB;
            bool isS = rem >= TILES_G;
            int ntile = isS ? rem - TILES_G : rem;
            const uint16_t* Wb = isS ? g_Wsb : g_Wgb;
            const float* bias = isS ? bs : bg;
            float* out = isS ? outS : outG;
            float* pmax = isS ? g_pmaxS : g_pmaxG;
            float* psum = isS ? g_psumS : g_psumG;
            const int V = isS ? VSENS : VGLOB;
            const int pstr = isS ? PSTR_S : PSTR_G;
            int m0 = mblk * 128, n0 = ntile * 128;

            // gate: all h2s rows <= m0+127 published
            if (ltid == 0) {
                unsigned tgt = (unsigned)(m0 + 128) * NR;
                while (ld_acquire(&g_cnt2[cpy * 32]) < tgt) {}
            }
            asm volatile("bar.sync 3, 256;" ::: "memory");
            if (ltid < 128) {
                int v = n0 + ltid;
                sBias[ltid] = (v < V) ? bias[v] : 0.f;
            }

            float acc[2][8][4];
#pragma unroll
            for (int mt = 0; mt < 2; ++mt)
#pragma unroll
                for (int nt = 0; nt < 8; ++nt)
#pragma unroll
                    for (int e = 0; e < 4; ++e) acc[mt][nt][e] = 0.f;

            auto issue = [&](int kc, int s) {
                int k0 = kc * 32;
#pragma unroll
                for (int p = 0; p < 2; ++p) {
                    int f = ltid + p * 256;
                    int row = f >> 2, seg = f & 3;
                    cp_async16(&sA[s][row * 40 + seg * 8],
                               &g_h2sb[(long)(m0 + row) * HD2 + k0 + seg * 8], 16);
                    int vr = n0 + row;
                    int srow = vr < V ? vr : 0;
                    cp_async16(&sB[s][row * 40 + seg * 8],
                               &Wb[(long)srow * HD2 + k0 + seg * 8], vr < V ? 16 : 0);
                }
                cp_commit();
            };

            issue(0, 0);
            for (int kc = 0; kc < 16; ++kc) {
                if (kc + 1 < 16) { issue(kc + 1, (kc + 1) & 1); cp_wait<1>(); }
                else             { cp_wait<0>(); }
                asm volatile("bar.sync 3, 256;" ::: "memory");
                const uint16_t* pA = sA[kc & 1];
                const uint16_t* pB = sB[kc & 1];
#pragma unroll
                for (int ks = 0; ks < 2; ++ks) {
                    int kk = ks * 16;
                    uint32_t a[2][4], b[8][2];
                    int ar = wm * 32 + (lane >> 2);
                    int ac = kk + (lane & 3) * 2;
#pragma unroll
                    for (int mt = 0; mt < 2; ++mt) {
                        const uint16_t* base = &pA[(ar + mt * 16) * 40 + ac];
                        a[mt][0] = *(const uint32_t*)(base);
                        a[mt][1] = *(const uint32_t*)(base + 8 * 40);
                        a[mt][2] = *(const uint32_t*)(base + 8);
                        a[mt][3] = *(const uint32_t*)(base + 8 * 40 + 8);
                    }
                    int br = wn * 64 + (lane >> 2);
#pragma unroll
                    for (int nt = 0; nt < 8; ++nt) {
                        const uint16_t* base = &pB[(br + nt * 8) * 40 + ac];
                        b[nt][0] = *(const uint32_t*)(base);
                        b[nt][1] = *(const uint32_t*)(base + 8);
                    }
#pragma unroll
                    for (int mt = 0; mt < 2; ++mt)
#pragma unroll
                        for (int nt = 0; nt < 8; ++nt) mma_bf16(acc[mt][nt], a[mt], b[nt]);
                }
                asm volatile("bar.sync 3, 256;" ::: "memory");
            }

            int rbase = wm * 32 + (lane >> 2);
            int cbase = wn * 64 + (lane & 3) * 2;
#pragma unroll
            for (int mt = 0; mt < 2; ++mt)
#pragma unroll
                for (int h = 0; h < 2; ++h) {
                    int rr = rbase + mt * 16 + h * 8;
                    long t = m0 + rr;
                    float xs[16];
                    float M = -CUDART_INF_F;
#pragma unroll
                    for (int nt = 0; nt < 8; ++nt)
#pragma unroll
                        for (int e = 0; e < 2; ++e) {
                            int cc = cbase + nt * 8 + e;
                            int v = n0 + cc;
                            float x = -CUDART_INF_F;
                            if (v < V) {
                                x = acc[mt][nt][h * 2 + e] + sBias[cc];
                                out[t * V + v] = x;
                                M = fmaxf(M, x);
                            }
                            xs[nt * 2 + e] = x;
                        }
                    float S = 0.f;
#pragma unroll
                    for (int i = 0; i < 16; ++i)
                        if (xs[i] != -CUDART_INF_F) S += __expf(xs[i] - M);
#pragma unroll
                    for (int o = 1; o <= 2; o <<= 1) {
                        float m2 = __shfl_xor_sync(~0u, M, o);
                        float s2 = __shfl_xor_sync(~0u, S, o);
                        lse_merge(M, S, m2, s2);
                    }
                    if ((lane & 3) == 0) { sM[rr * 2 + wn] = M; sS_[rr * 2 + wn] = S; }
                }
            asm volatile("bar.sync 3, 256;" ::: "memory");
            if (ltid < 128) {
                float M = sM[ltid * 2], S = sS_[ltid * 2];
                lse_merge(M, S, sM[ltid * 2 + 1], sS_[ltid * 2 + 1]);
                long t = m0 + ltid;
                pmax[t * pstr + ntile] = M;
                psum[t * pstr + ntile] = S;
            }
            asm volatile("bar.sync 3, 256;" ::: "memory");
        }
    }
}

// ------------------------- per-row LSE reduction -------------------------
__global__ void lse_kernel() {
    int t = blockIdx.x;
    int which = blockIdx.y;
    const float* pm = which ? g_pmaxS : g_pmaxG;
    const float* ps = which ? g_psumS : g_psumG;
    int nb = which ? TILES_S : TILES_G;
    int pstr = which ? PSTR_S : PSTR_G;
    float M = -CUDART_INF_F, S = 0.f;
    for (int i = threadIdx.x; i < nb; i += 128)
        lse_merge(M, S, pm[(long)t * pstr + i], ps[(long)t * pstr + i]);
#pragma unroll
    for (int o = 16; o; o >>= 1) {
        float m2 = __shfl_xor_sync(~0u, M, o);
        float s2 = __shfl_xor_sync(~0u, S, o);
        lse_merge(M, S, m2, s2);
    }
    __shared__ float sm_[4], ss_[4];
    int w = threadIdx.x >> 5;
    if ((threadIdx.x & 31) == 0) { sm_[w] = M; ss_[w] = S; }
    __syncthreads();
    if (threadIdx.x == 0) {
        for (int k = 1; k < 4; ++k) lse_merge(M, S, sm_[k], ss_[k]);
        float lse = M + logf(S);
        if (which) g_lseS[t] = lse; else g_lseG[t] = lse;
    }
}

// ------------------------- in-place logp = logit - lse (row from blockIdx.y) -------------
__global__ void sub_kernel(float* __restrict__ base, int which, int V) {
    int t = blockIdx.y;
    float l = (which ? g_lseS : g_lseG)[t];
    float4* row = (float4*)(base + (size_t)t * V);
    int n4 = V >> 2;
    for (int i = blockIdx.x * blockDim.x + threadIdx.x; i < n4; i += gridDim.x * blockDim.x) {
        float4 v = row[i];
        v.x -= l; v.y -= l; v.z -= l; v.w -= l;
        row[i] = v;
    }
}

// ------------------------- launcher -------------------------
extern "C" void kernel_launch(void* const* d_in, const int* in_sizes, int n_in,
                              void* d_out, int out_size) {
    const float* X  = (const float*)d_in[0];
    const float* W1 = (const float*)d_in[1];
    const float* b1 = (const float*)d_in[2];
    const float* W2 = (const float*)d_in[3];
    const float* b2 = (const float*)d_in[4];
    const float* Wg = (const float*)d_in[5];
    const float* bg = (const float*)d_in[6];
    const float* Ws = (const float*)d_in[7];
    const float* bs = (const float*)d_in[8];
    const int*  idx = (const int*)d_in[9];
    float* outG = (float*)d_out;
    float* outS = outG + (size_t)T_STEPS * VGLOB;

    uint16_t* wgb; cudaGetSymbolAddress((void**)&wgb, g_Wgb);
    uint16_t* wsb; cudaGetSymbolAddress((void**)&wsb, g_Wsb);

    init_kernel<<<64, 256>>>();
    u1_kernel<<<dim3(16, 16), 256>>>(X, W1, b1, idx);
    convert_kernel<<<2048, 256>>>(Wg, wgb, VGLOB * HD2 / 4);
    convert_kernel<<<2048, 256>>>(Ws, wsb, VSENS * HD2 / 4);
    fused_kernel<<<NR, 512>>>(W1, W2, b2, bg, bs, outG, outS);
    lse_kernel<<<dim3(T_STEPS, 2), 128>>>();
    sub_kernel<<<dim3(49, T_STEPS), 256>>>(outG, 0, VGLOB);
    sub_kernel<<<dim3(25, T_STEPS), 256>>>(outS, 1, VSENS);
}

// round 15
// speedup vs baseline: 3.6390x; 1.0085x over previous
#include <cuda_runtime.h>
#include <cuda_bf16.h>
#include <cstdint>
#include <math_constants.h>

#define T_STEPS 1024
#define DIM     300
#define HD1     1024
#define HD2     512
#define VGLOB   50000
#define VSENS   25000
#define NR      128          // rnn CTAs: 1024 = 128*8, 512 = 128*4

#define TILES_G 391
#define TILES_S 196
#define TPB     (TILES_G + TILES_S)   // 587 tiles per m-block
#define NTILES  (8 * TPB)             // 4696
#define PSTR_G  392
#define PSTR_S  200

// dynamic smem layout
#define GRP_BYTES 43520   // sA 20480 + sB 20480 + bias 512 + sM 1024 + sS 1024
#define DYN_BYTES (256 + 2 * GRP_BYTES)

// ------------------------- device scratch -------------------------
__device__ __align__(16) float g_U1[T_STEPS * HD1];
__device__ __align__(16) float g_h1rep[8][4][HD1];   // [copy][parity r&3][HD1]
__device__ __align__(16) float g_h2rep[8][2][HD2];   // [copy][parity][HD2]
__device__ __align__(128) unsigned g_cnt1[8 * 32];
__device__ __align__(128) unsigned g_cnt2[8 * 32];
__device__ __align__(128) unsigned g_tileCtr[32];
__device__ float g_pmaxG[T_STEPS * PSTR_G];
__device__ float g_psumG[T_STEPS * PSTR_G];
__device__ float g_pmaxS[T_STEPS * PSTR_S];
__device__ float g_psumS[T_STEPS * PSTR_S];
__device__ float g_lseG[T_STEPS];
__device__ float g_lseS[T_STEPS];
// bf16 operands for the logits GEMM
__device__ __align__(16) uint16_t g_h2sb[T_STEPS * HD2];
__device__ __align__(16) uint16_t g_Wgb[(size_t)VGLOB * HD2];
__device__ __align__(16) uint16_t g_Wsb[(size_t)VSENS * HD2];

// ------------------------- helpers -------------------------
__device__ __forceinline__ void red_release(unsigned* p, unsigned v) {
    asm volatile("red.release.gpu.global.add.u32 [%0], %1;" :: "l"(p), "r"(v) : "memory");
}
__device__ __forceinline__ unsigned ld_acquire(const unsigned* p) {
    unsigned v;
    asm volatile("ld.acquire.gpu.global.u32 %0, [%1];" : "=r"(v) : "l"(p) : "memory");
    return v;
}
__device__ __forceinline__ void stcg4(float* p, float4 v) {
    asm volatile("st.global.cg.v4.f32 [%0], {%1,%2,%3,%4};"
                 :: "l"(p), "f"(v.x), "f"(v.y), "f"(v.z), "f"(v.w) : "memory");
}
__device__ __forceinline__ void bar_sync(int id) {
    asm volatile("bar.sync %0, 256;" :: "r"(id) : "memory");
}

__device__ __forceinline__ void mma_bf16(float c[4], const uint32_t a[4], const uint32_t b[2]) {
    asm volatile(
        "mma.sync.aligned.m16n8k16.row.col.f32.bf16.bf16.f32 "
        "{%0,%1,%2,%3}, {%4,%5,%6,%7}, {%8,%9}, {%0,%1,%2,%3};"
        : "+f"(c[0]), "+f"(c[1]), "+f"(c[2]), "+f"(c[3])
        : "r"(a[0]), "r"(a[1]), "r"(a[2]), "r"(a[3]), "r"(b[0]), "r"(b[1]));
}

__device__ __forceinline__ void cp_async16(void* dst_smem, const void* src, int src_bytes) {
    uint32_t d = (uint32_t)__cvta_generic_to_shared(dst_smem);
    asm volatile("cp.async.cg.shared.global [%0], [%1], 16, %2;"
                 :: "r"(d), "l"(src), "r"(src_bytes));
}
__device__ __forceinline__ void cp_commit() { asm volatile("cp.async.commit_group;"); }
template <int N>
__device__ __forceinline__ void cp_wait() { asm volatile("cp.async.wait_group %0;" :: "n"(N)); }

__device__ __forceinline__ void lse_merge(float& M, float& S, float m, float s) {
    float nm = fmaxf(M, m);
    if (nm == -CUDART_INF_F) { M = nm; S = 0.f; return; }
    S = S * __expf(M - nm) + s * __expf(m - nm);
    M = nm;
}

__device__ __forceinline__ uint32_t pack_bf16(float a, float b) {
    __nv_bfloat16 ba = __float2bfloat16(a), bb = __float2bfloat16(b);
    return (uint32_t)reinterpret_cast<unsigned short&>(ba) |
           ((uint32_t)reinterpret_cast<unsigned short&>(bb) << 16);
}

// ------------------------- init -------------------------
__global__ void init_kernel() {
    int tid = threadIdx.x + blockIdx.x * blockDim.x;
    int stride = gridDim.x * blockDim.x;
    if (tid < 8 * 32) { g_cnt1[tid] = 0u; g_cnt2[tid] = 0u; }
    if (tid < 32) g_tileCtr[tid] = 0u;
    for (int i = tid; i < 8 * 4 * HD1; i += stride) ((float*)g_h1rep)[i] = 0.f;
    for (int i = tid; i < 8 * 2 * HD2; i += stride) ((float*)g_h2rep)[i] = 0.f;
}

// ------------------------- fp32 -> bf16 weight conversion -------------------------
__global__ void convert_kernel(const float* __restrict__ src, uint16_t* __restrict__ dst, int n4) {
    int i = blockIdx.x * blockDim.x + threadIdx.x;
    int stride = gridDim.x * blockDim.x;
    uint32_t* d32 = (uint32_t*)dst;
    const float4* s4 = (const float4*)src;
    for (; i < n4; i += stride) {
        float4 v = s4[i];
        d32[2 * i]     = pack_bf16(v.x, v.y);
        d32[2 * i + 1] = pack_bf16(v.z, v.w);
    }
}

// ------------------------- U1 = E @ W1e^T + b1 -------------------------
__global__ void __launch_bounds__(256) u1_kernel(const float* __restrict__ X,
                                                 const float* __restrict__ W1,
                                                 const float* __restrict__ b1,
                                                 const int* __restrict__ idx) {
    __shared__ float sA[20][64];
    __shared__ float sB[20][64];
    __shared__ int sidx[64];
    int tid = threadIdx.x;
    int t0 = blockIdx.y * 64, i0 = blockIdx.x * 64;
    if (tid < 64) sidx[tid] = idx[t0 + tid];
    __syncthreads();
    float acc[4][4];
#pragma unroll
    for (int a = 0; a < 4; ++a)
#pragma unroll
        for (int b = 0; b < 4; ++b) acc[a][b] = 0.f;
    int tx = tid & 15, ty = tid >> 4;
    for (int kc = 0; kc < 15; ++kc) {
        int k0 = kc * 20;
        for (int i = tid; i < 1280; i += 256) {
            int k = i >> 6, m = i & 63;
            sA[k][m] = X[(long)sidx[m] * DIM + k0 + k];
            sB[k][m] = W1[(long)(i0 + m) * (DIM + HD1) + k0 + k];
        }
        __syncthreads();
#pragma unroll
        for (int k = 0; k < 20; ++k) {
            float a[4], b[4];
#pragma unroll
            for (int e = 0; e < 4; ++e) { a[e] = sA[k][ty * 4 + e]; b[e] = sB[k][tx * 4 + e]; }
#pragma unroll
            for (int ii = 0; ii < 4; ++ii)
#pragma unroll
                for (int jj = 0; jj < 4; ++jj) acc[ii][jj] += a[ii] * b[jj];
        }
        __syncthreads();
    }
#pragma unroll
    for (int ii = 0; ii < 4; ++ii)
#pragma unroll
        for (int jj = 0; jj < 4; ++jj) {
            int t = t0 + ty * 4 + ii, n = i0 + tx * 4 + jj;
            g_U1[t * HD1 + n] = acc[ii][jj] + b1[n];
        }
}

// ------------------------- logits tile worker (256 threads, named barrier) ------------
// Fetches tiles from the global atomic queue (tt order = m-block monotonic),
// gates each tile on cnt2 >= (m0+128)*NR, computes the 128x128 bf16 GEMM tile
// with fused bias + streaming (max, sumexp) partials.
__device__ __noinline__ void tile_worker(char* grp, int ltid, int barid, int cpy,
                                         const float* bg, const float* bs,
                                         float* outG, float* outS, int* sTT) {
    uint16_t* sA = (uint16_t*)grp;                   // [2][128*40]
    uint16_t* sB = (uint16_t*)(grp + 20480);         // [2][128*40]
    float* sBias = (float*)(grp + 40960);            // [128]
    float* sM    = (float*)(grp + 41472);            // [128*2]
    float* sS_   = (float*)(grp + 42496);            // [128*2]
    int lane = ltid & 31;
    int lwarp = ltid >> 5;
    int wm = lwarp & 3, wn = lwarp >> 2;

    for (;;) {
        if (ltid == 0) *sTT = (int)atomicAdd(&g_tileCtr[0], 1u);
        bar_sync(barid);
        int tt = *sTT;
        bar_sync(barid);             // all read sTT before next overwrite
        if (tt >= NTILES) break;

        int mblk = tt / TPB, rem = tt % TPB;
        bool isS = rem >= TILES_G;
        int ntile = isS ? rem - TILES_G : rem;
        const uint16_t* Wb = isS ? g_Wsb : g_Wgb;
        const float* bias = isS ? bs : bg;
        float* out = isS ? outS : outG;
        float* pmax = isS ? g_pmaxS : g_pmaxG;
        float* psum = isS ? g_psumS : g_psumG;
        const int V = isS ? VSENS : VGLOB;
        const int pstr = isS ? PSTR_S : PSTR_G;
        int m0 = mblk * 128, n0 = ntile * 128;

        if (ltid == 0) {             // gate: h2s rows <= m0+127 published
            unsigned tgt = (unsigned)(m0 + 128) * NR;
            while (ld_acquire(&g_cnt2[cpy * 32]) < tgt) {}
        }
        if (ltid < 128) {
            int v = n0 + ltid;
            sBias[ltid] = (v < V) ? bias[v] : 0.f;
        }
        bar_sync(barid);

        float acc[2][8][4];
#pragma unroll
        for (int mt = 0; mt < 2; ++mt)
#pragma unroll
            for (int nt = 0; nt < 8; ++nt)
#pragma unroll
                for (int e = 0; e < 4; ++e) acc[mt][nt][e] = 0.f;

        auto issue = [&](int kc, int s) {
            int k0 = kc * 32;
#pragma unroll
            for (int p = 0; p < 2; ++p) {
                int f = ltid + p * 256;
                int row = f >> 2, seg = f & 3;
                cp_async16(&sA[s * 5120 + row * 40 + seg * 8],
                           &g_h2sb[(long)(m0 + row) * HD2 + k0 + seg * 8], 16);
                int vr = n0 + row;
                int srow = vr < V ? vr : 0;
                cp_async16(&sB[s * 5120 + row * 40 + seg * 8],
                           &Wb[(long)srow * HD2 + k0 + seg * 8], vr < V ? 16 : 0);
            }
            cp_commit();
        };

        issue(0, 0);
        for (int kc = 0; kc < 16; ++kc) {
            if (kc + 1 < 16) { issue(kc + 1, (kc + 1) & 1); cp_wait<1>(); }
            else             { cp_wait<0>(); }
            bar_sync(barid);
            const uint16_t* pA = sA + (kc & 1) * 5120;
            const uint16_t* pB = sB + (kc & 1) * 5120;
#pragma unroll
            for (int ks = 0; ks < 2; ++ks) {
                int kk = ks * 16;
                uint32_t a[2][4], b[8][2];
                int ar = wm * 32 + (lane >> 2);
                int ac = kk + (lane & 3) * 2;
#pragma unroll
                for (int mt = 0; mt < 2; ++mt) {
                    const uint16_t* base = &pA[(ar + mt * 16) * 40 + ac];
                    a[mt][0] = *(const uint32_t*)(base);
                    a[mt][1] = *(const uint32_t*)(base + 8 * 40);
                    a[mt][2] = *(const uint32_t*)(base + 8);
                    a[mt][3] = *(const uint32_t*)(base + 8 * 40 + 8);
                }
                int br = wn * 64 + (lane >> 2);
#pragma unroll
                for (int nt = 0; nt < 8; ++nt) {
                    const uint16_t* base = &pB[(br + nt * 8) * 40 + ac];
                    b[nt][0] = *(const uint32_t*)(base);
                    b[nt][1] = *(const uint32_t*)(base + 8);
                }
#pragma unroll
                for (int mt = 0; mt < 2; ++mt)
#pragma unroll
                    for (int nt = 0; nt < 8; ++nt) mma_bf16(acc[mt][nt], a[mt], b[nt]);
            }
            bar_sync(barid);
        }

        int rbase = wm * 32 + (lane >> 2);
        int cbase = wn * 64 + (lane & 3) * 2;
#pragma unroll
        for (int mt = 0; mt < 2; ++mt)
#pragma unroll
            for (int h = 0; h < 2; ++h) {
                int rr = rbase + mt * 16 + h * 8;
                long t = m0 + rr;
                float xs[16];
                float M = -CUDART_INF_F;
#pragma unroll
                for (int nt = 0; nt < 8; ++nt)
#pragma unroll
                    for (int e = 0; e < 2; ++e) {
                        int cc = cbase + nt * 8 + e;
                        int v = n0 + cc;
                        float x = -CUDART_INF_F;
                        if (v < V) {
                            x = acc[mt][nt][h * 2 + e] + sBias[cc];
                            out[t * V + v] = x;
                            M = fmaxf(M, x);
                        }
                        xs[nt * 2 + e] = x;
                    }
                float S = 0.f;
#pragma unroll
                for (int i = 0; i < 16; ++i)
                    if (xs[i] != -CUDART_INF_F) S += __expf(xs[i] - M);
#pragma unroll
                for (int o = 1; o <= 2; o <<= 1) {
                    float m2 = __shfl_xor_sync(~0u, M, o);
                    float s2 = __shfl_xor_sync(~0u, S, o);
                    lse_merge(M, S, m2, s2);
                }
                if ((lane & 3) == 0) { sM[rr * 2 + wn] = M; sS_[rr * 2 + wn] = S; }
            }
        bar_sync(barid);
        if (ltid < 128) {
            float M = sM[ltid * 2], S = sS_[ltid * 2];
            lse_merge(M, S, sM[ltid * 2 + 1], sS_[ltid * 2 + 1]);
            long t = m0 + ltid;
            pmax[t * pstr + ntile] = M;
            psum[t * pstr + ntile] = S;
        }
        bar_sync(barid);
    }
}

// ------------------------- fused RNN + logits kernel (512 threads) -------------------
// Warps 0-3: h1 chain (bar 1). Warps 4-7: h2 chain (bar 2). Warps 8-15: tile
// worker group A (bar 3) from kernel start. After the RNN loops retire, warps
// 0-7 become tile worker group B (bar 4) on the same dynamic queue.
__global__ void __launch_bounds__(512, 1) fused_kernel(const float* __restrict__ W1,
                                                       const float* __restrict__ W2,
                                                       const float* __restrict__ b2,
                                                       const float* __restrict__ bg,
                                                       const float* __restrict__ bs,
                                                       float* __restrict__ outG,
                                                       float* __restrict__ outS) {
    extern __shared__ __align__(16) char dyn[];
    float* sP1 = (float*)dyn;             // 32 floats
    float* sP2 = (float*)(dyn + 128);     // 16 floats
    int* sTT   = (int*)(dyn + 192);       // [2]
    char* grpA = dyn + 256;
    char* grpB = grpA + GRP_BYTES;

    int tid = threadIdx.x, c = blockIdx.x;
    int lane = tid & 31;
    int cpy = c & 7;

    if (tid < 128) {
        // =================== h1 group (warps 0-3) ===================
        int w = tid >> 5;
        float w1r[8][8];   // [jj][q]
#pragma unroll
        for (int q = 0; q < 8; ++q) {
            const float* p = W1 + (long)(c * 8 + q) * (DIM + HD1) + DIM;
#pragma unroll
            for (int jj = 0; jj < 8; ++jj)
                w1r[jj][q] = p[w * 256 + jj * 32 + lane];
        }

        for (int r = 0; r < T_STEPS; ++r) {
            float u1v = 0.f;
            if (tid < 8) u1v = __ldg(&g_U1[r * HD1 + c * 8 + tid]);
            if (tid == 0) {
                if (r >= 4) {   // WAR gate (usually satisfied), overlapping cnt1 wait
                    unsigned t2 = (unsigned)(r - 3) * NR;
                    while (ld_acquire(&g_cnt2[cpy * 32]) < t2) {}
                }
                if (r > 0) {
                    unsigned t1 = (unsigned)r * NR;
                    while (ld_acquire(&g_cnt1[cpy * 32]) < t1) {}
                }
            }
            asm volatile("bar.sync 1, 128;" ::: "memory");

            const float* h1p = g_h1rep[cpy][(r + 3) & 3];   // h1(r-1)
            float p1[8] = {0, 0, 0, 0, 0, 0, 0, 0};
#pragma unroll
            for (int jj = 0; jj < 8; ++jj) {
                float h = __ldcg(&h1p[w * 256 + jj * 32 + lane]);
#pragma unroll
                for (int q = 0; q < 8; ++q) p1[q] += w1r[jj][q] * h;
            }
#pragma unroll
            for (int q = 0; q < 8; ++q)
#pragma unroll
                for (int o = 16; o; o >>= 1) p1[q] += __shfl_xor_sync(~0u, p1[q], o);
            if (lane == 0) {
#pragma unroll
                for (int q = 0; q < 8; ++q) sP1[q * 4 + w] = p1[q];
            }
            asm volatile("bar.sync 1, 128;" ::: "memory");

            if (w == 0) {
                float s = 0.f;
                if (lane < 8) {
                    float4 ps = *(const float4*)&sP1[lane * 4];
                    s = u1v + ps.x + ps.y + ps.z + ps.w;
                    s = s > 0.f ? s : 0.01f * s;
                }
                float sv[8];
#pragma unroll
                for (int q = 0; q < 8; ++q) sv[q] = __shfl_sync(~0u, s, q);
                if (lane < 8) {
                    float* dst = &g_h1rep[lane][r & 3][c * 8];
                    stcg4(dst,     make_float4(sv[0], sv[1], sv[2], sv[3]));
                    stcg4(dst + 4, make_float4(sv[4], sv[5], sv[6], sv[7]));
                    red_release(&g_cnt1[lane * 32], 1u);
                }
            }
        }
        // join group B tile work
        tile_worker(grpB, tid, 4, cpy, bg, bs, outG, outS, &sTT[1]);
    } else if (tid < 256) {
        // =================== h2 group (warps 4-7) ===================
        int w = (tid >> 5) - 4;
        float w2a[8][4], w2b[4][4];
#pragma unroll
        for (int q = 0; q < 4; ++q) {
            const float* p = W2 + (long)(c * 4 + q) * (HD1 + HD2);
#pragma unroll
            for (int jj = 0; jj < 8; ++jj)
                w2a[jj][q] = p[w * 256 + jj * 32 + lane];
#pragma unroll
            for (int jj = 0; jj < 4; ++jj)
                w2b[jj][q] = p[HD1 + w * 128 + jj * 32 + lane];
        }
        float b2v = 0.f;
        if (tid >= 128 && tid < 132) b2v = b2[c * 4 + (tid - 128)];

        for (int r = 1; r <= T_STEPS; ++r) {
            if (tid == 128) {
                unsigned t1 = (unsigned)r * NR;
                while (ld_acquire(&g_cnt1[cpy * 32]) < t1) {}
                if (r > 1) {
                    unsigned t2 = (unsigned)(r - 1) * NR;
                    while (ld_acquire(&g_cnt2[cpy * 32]) < t2) {}
                }
            }
            asm volatile("bar.sync 2, 128;" ::: "memory");

            const float* h1p = g_h1rep[cpy][(r + 3) & 3];   // h1(r-1)
            const float* h2p = g_h2rep[cpy][r & 1];          // h2(r-2)
            float p2[4] = {0, 0, 0, 0};
#pragma unroll
            for (int jj = 0; jj < 8; ++jj) {
                float h = __ldcg(&h1p[w * 256 + jj * 32 + lane]);
#pragma unroll
                for (int q = 0; q < 4; ++q) p2[q] += w2a[jj][q] * h;
            }
#pragma unroll
            for (int jj = 0; jj < 4; ++jj) {
                float h = __ldcg(&h2p[w * 128 + jj * 32 + lane]);
#pragma unroll
                for (int q = 0; q < 4; ++q) p2[q] += w2b[jj][q] * h;
            }
#pragma unroll
            for (int q = 0; q < 4; ++q)
#pragma unroll
                for (int o = 16; o; o >>= 1) p2[q] += __shfl_xor_sync(~0u, p2[q], o);
            if (lane == 0) {
#pragma unroll
                for (int q = 0; q < 4; ++q) sP2[q * 4 + w] = p2[q];
            }
            asm volatile("bar.sync 2, 128;" ::: "memory");

            if (w == 0) {
                float s = 0.f;
                if (lane < 4) {
                    float4 ps = *(const float4*)&sP2[lane * 4];
                    s = b2v + ps.x + ps.y + ps.z + ps.w;
                    s = s > 0.f ? s : 0.01f * s;
                }
                float sv[4];
#pragma unroll
                for (int q = 0; q < 4; ++q) sv[q] = __shfl_sync(~0u, s, q);
                if (lane < 8) {
                    stcg4(&g_h2rep[lane][(r + 1) & 1][c * 4],
                          make_float4(sv[0], sv[1], sv[2], sv[3]));
                    // h2sb stored by the SAME lanes that release cnt2
                    unsigned long long hv =
                        (unsigned long long)pack_bf16(sv[0], sv[1]) |
                        ((unsigned long long)pack_bf16(sv[2], sv[3]) << 32);
                    *(unsigned long long*)&g_h2sb[(r - 1) * HD2 + c * 4] = hv;
                    red_release(&g_cnt2[lane * 32], 1u);
                }
            }
        }
        // join group B tile work (tid 128..255 -> ltid 128..255? normalize)
        tile_worker(grpB, tid - 0 >= 128 ? tid - 0 : tid, 4, cpy, bg, bs, outG, outS, &sTT[1]);
    } else {
        // =================== tile worker group A (warps 8-15) ===================
        tile_worker(grpA, tid - 256, 3, cpy, bg, bs, outG, outS, &sTT[0]);
    }
}

// ------------------------- per-row LSE reduction -------------------------
__global__ void lse_kernel() {
    int t = blockIdx.x;
    int which = blockIdx.y;
    const float* pm = which ? g_pmaxS : g_pmaxG;
    const float* ps = which ? g_psumS : g_psumG;
    int nb = which ? TILES_S : TILES_G;
    int pstr = which ? PSTR_S : PSTR_G;
    float M = -CUDART_INF_F, S = 0.f;
    for (int i = threadIdx.x; i < nb; i += 128)
        lse_merge(M, S, pm[(long)t * pstr + i], ps[(long)t * pstr + i]);
#pragma unroll
    for (int o = 16; o; o >>= 1) {
        float m2 = __shfl_xor_sync(~0u, M, o);
        float s2 = __shfl_xor_sync(~0u, S, o);
        lse_merge(M, S, m2, s2);
    }
    __shared__ float sm_[4], ss_[4];
    int w = threadIdx.x >> 5;
    if ((threadIdx.x & 31) == 0) { sm_[w] = M; ss_[w] = S; }
    __syncthreads();
    if (threadIdx.x == 0) {
        for (int k = 1; k < 4; ++k) lse_merge(M, S, sm_[k], ss_[k]);
        float lse = M + logf(S);
        if (which) g_lseS[t] = lse; else g_lseG[t] = lse;
    }
}

// ------------------------- in-place logp = logit - lse (row from blockIdx.y) -------------
__global__ void sub_kernel(float* __restrict__ base, int which, int V) {
    int t = blockIdx.y;
    float l = (which ? g_lseS : g_lseG)[t];
    float4* row = (float4*)(base + (size_t)t * V);
    int n4 = V >> 2;
    for (int i = blockIdx.x * blockDim.x + threadIdx.x; i < n4; i += gridDim.x * blockDim.x) {
        float4 v = row[i];
        v.x -= l; v.y -= l; v.z -= l; v.w -= l;
        row[i] = v;
    }
}

// ------------------------- launcher -------------------------
extern "C" void kernel_launch(void* const* d_in, const int* in_sizes, int n_in,
                              void* d_out, int out_size) {
    const float* X  = (const float*)d_in[0];
    const float* W1 = (const float*)d_in[1];
    const float* b1 = (const float*)d_in[2];
    const float* W2 = (const float*)d_in[3];
    const float* b2 = (const float*)d_in[4];
    const float* Wg = (const float*)d_in[5];
    const float* bg = (const float*)d_in[6];
    const float* Ws = (const float*)d_in[7];
    const float* bs = (const float*)d_in[8];
    const int*  idx = (const int*)d_in[9];
    float* outG = (float*)d_out;
    float* outS = outG + (size_t)T_STEPS * VGLOB;

    uint16_t* wgb; cudaGetSymbolAddress((void**)&wgb, g_Wgb);
    uint16_t* wsb; cudaGetSymbolAddress((void**)&wsb, g_Wsb);

    cudaFuncSetAttribute(fused_kernel, cudaFuncAttributeMaxDynamicSharedMemorySize, DYN_BYTES);

    init_kernel<<<64, 256>>>();
    u1_kernel<<<dim3(16, 16), 256>>>(X, W1, b1, idx);
    convert_kernel<<<2048, 256>>>(Wg, wgb, VGLOB * HD2 / 4);
    convert_kernel<<<2048, 256>>>(Ws, wsb, VSENS * HD2 / 4);
    fused_kernel<<<NR, 512, DYN_BYTES>>>(W1, W2, b2, bg, bs, outG, outS);
    lse_kernel<<<dim3(T_STEPS, 2), 128>>>();
    sub_kernel<<<dim3(49, T_STEPS), 256>>>(outG, 0, VGLOB);
    sub_kernel<<<dim3(25, T_STEPS), 256>>>(outS, 1, VSENS);
}